// round 1
// baseline (speedup 1.0000x reference)
#include <cuda_runtime.h>
#include <math.h>

// Problem constants (fixed by the reference)
#define NTOK 2048            // B*S
#define DDIM 1024
#define FDIM 4096
#define NEXP 8
#define KTOP 2
#define NLAY 6
#define RTOT (NTOK*KTOP)     // 4096 gathered rows per layer

// ---------------- scratch (static device globals; no allocation) ----------------
__device__ float g_xn[NTOK*DDIM];                 // layernormed activations
__device__ float g_probs[NTOK*NEXP];              // softmax probs (for aux loss)
__device__ int   g_topi[NTOK*KTOP];
__device__ float g_topv[NTOK*KTOP];
__device__ int   g_cnt[NEXP];
__device__ int   g_off[NEXP];
__device__ int   g_cur[NEXP];
__device__ int   g_row_tok[RTOT];                 // gathered row -> token
__device__ int   g_tok_row[RTOT];                 // (token,slot) -> gathered row
__device__ float g_H[(size_t)RTOT*FDIM];          // FFN hidden (64 MB)
__device__ float g_Y[(size_t)RTOT*DDIM];          // FFN out per (token,expert)
__device__ float g_loss;

__device__ __forceinline__ float gelu_tanh(float x){
    // jax.nn.gelu default: approximate=True (tanh form)
    float x3 = x*x*x;
    float t  = tanhf(0.7978845608028654f*(x + 0.044715f*x3));
    return 0.5f*x*(1.0f+t);
}

// ---------------- init: out <- x, loss <- 0 ----------------
__global__ void init_kernel(const float* __restrict__ x, float* __restrict__ out){
    int i = blockIdx.x*blockDim.x + threadIdx.x;   // exactly NTOK*DDIM threads
    out[i] = x[i];
    if (i==0) g_loss = 0.0f;
}

// ---------------- layernorm: g_xn <- LN(out) ----------------
__global__ void ln_kernel(const float* __restrict__ xin){
    int t = blockIdx.x, tid = threadIdx.x;
    __shared__ float red[256];
    float v[4];
    #pragma unroll
    for (int q=0;q<4;q++) v[q] = xin[(size_t)t*DDIM + q*256 + tid];
    float s = v[0]+v[1]+v[2]+v[3];
    red[tid]=s; __syncthreads();
    for (int o=128;o>0;o>>=1){ if(tid<o) red[tid]+=red[tid+o]; __syncthreads(); }
    float mean = red[0]*(1.0f/DDIM);
    __syncthreads();
    float s2=0.f;
    #pragma unroll
    for (int q=0;q<4;q++){ v[q]-=mean; s2 += v[q]*v[q]; }
    red[tid]=s2; __syncthreads();
    for (int o=128;o>0;o>>=1){ if(tid<o) red[tid]+=red[tid+o]; __syncthreads(); }
    float inv = 1.0f/sqrtf(red[0]*(1.0f/DDIM) + 1e-5f);
    #pragma unroll
    for (int q=0;q<4;q++) g_xn[(size_t)t*DDIM + q*256 + tid] = v[q]*inv;
}

// ---------------- router: logits, softmax, top-2 ----------------
__global__ void router_kernel(const float* __restrict__ wr){
    int t = blockIdx.x, tid = threadIdx.x;
    __shared__ float sx[DDIM];
    __shared__ float slog[NEXP];
    #pragma unroll
    for (int q=0;q<4;q++) sx[q*256+tid] = g_xn[(size_t)t*DDIM + q*256 + tid];
    __syncthreads();
    int e = tid>>5, lane = tid&31;     // 8 warps = 8 experts
    float acc = 0.f;
    for (int d=lane; d<DDIM; d+=32) acc += sx[d]*wr[d*NEXP+e];
    #pragma unroll
    for (int o=16;o>0;o>>=1) acc += __shfl_down_sync(0xffffffffu, acc, o);
    if (lane==0) slog[e]=acc;
    __syncthreads();
    if (tid==0){
        float p[NEXP];
        float m = slog[0];
        #pragma unroll
        for (int i=1;i<NEXP;i++) m = fmaxf(m, slog[i]);
        float ssum = 0.f;
        #pragma unroll
        for (int i=0;i<NEXP;i++){ p[i]=expf(slog[i]-m); ssum+=p[i]; }
        #pragma unroll
        for (int i=0;i<NEXP;i++){ p[i] = p[i]/ssum; g_probs[t*NEXP+i]=p[i]; }
        int i1=0; float v1=p[0];
        #pragma unroll
        for (int i=1;i<NEXP;i++) if (p[i]>v1){ v1=p[i]; i1=i; }
        int i2=-1; float v2=-1e30f;
        #pragma unroll
        for (int i=0;i<NEXP;i++) if (i!=i1 && p[i]>v2){ v2=p[i]; i2=i; }
        g_topi[t*2+0]=i1; g_topv[t*2+0]=v1;
        g_topi[t*2+1]=i2; g_topv[t*2+1]=v2;
    }
}

// ---------------- per-layer stats: counts, offsets, aux loss ----------------
__global__ void stats_kernel(){
    int tid = threadIdx.x;
    __shared__ int   sc[NEXP];
    __shared__ float red[256];
    __shared__ float sexp[NEXP];
    if (tid<NEXP) sc[tid]=0;
    __syncthreads();
    for (int i=tid;i<RTOT;i+=256) atomicAdd(&sc[g_topi[i]], 1);
    float myp[NEXP];
    #pragma unroll
    for (int e=0;e<NEXP;e++) myp[e]=0.f;
    for (int t=tid;t<NTOK;t+=256){
        #pragma unroll
        for (int e=0;e<NEXP;e++) myp[e] += g_probs[t*NEXP+e];
    }
    __syncthreads();
    for (int e=0;e<NEXP;e++){
        red[tid]=myp[e]; __syncthreads();
        for (int o=128;o>0;o>>=1){ if(tid<o) red[tid]+=red[tid+o]; __syncthreads(); }
        if (tid==0) sexp[e]=red[0];
        __syncthreads();
    }
    if (tid==0){
        float loss = 0.f;
        #pragma unroll
        for (int e=0;e<NEXP;e++)
            loss += ((float)sc[e]*(1.0f/NTOK)) * (sexp[e]*(1.0f/NTOK));
        g_loss += (float)NEXP * loss;
        int off = 0;
        #pragma unroll
        for (int e=0;e<NEXP;e++){ g_cnt[e]=sc[e]; g_off[e]=off; g_cur[e]=0; off+=sc[e]; }
    }
}

// ---------------- placement: build gather lists ----------------
__global__ void place_kernel(){
    int i = blockIdx.x*blockDim.x + threadIdx.x;
    if (i >= RTOT) return;
    int e = g_topi[i];
    int r = g_off[e] + atomicAdd(&g_cur[e], 1);
    g_row_tok[r] = i>>1;
    g_tok_row[i] = r;
}

// ---------------- GEMM1: H = gelu(gather(xn) @ w1[e] + b1[e]) ----------------
__global__ void __launch_bounds__(256) gemm1_kernel(const float* __restrict__ w1l,
                                                    const float* __restrict__ b1l){
    int e   = blockIdx.z;
    int cnt = g_cnt[e];
    int m0  = blockIdx.y*64;
    if (m0 >= cnt) return;
    int off = g_off[e];
    int n0  = blockIdx.x*64;

    __shared__ float As[16][65];
    __shared__ __align__(16) float Bs[16][64];
    __shared__ int stok[64];
    int tid = threadIdx.x;
    if (tid < 64){
        int i = m0 + tid; if (i >= cnt) i = cnt-1;
        stok[tid] = g_row_tok[off + i];
    }
    __syncthreads();

    int tx = tid & 15, ty = tid >> 4;
    int arow = tid >> 2, ak4 = (tid & 3)*4;
    int bk = tid >> 4, bc4 = (tid & 15)*4;

    const float* aptr = g_xn + (size_t)stok[arow]*DDIM + ak4;
    const float* bptr = w1l + (size_t)e*DDIM*FDIM + (size_t)bk*FDIM + n0 + bc4;

    float acc[4][4] = {};
    for (int k0=0;k0<DDIM;k0+=16){
        float4 av = *(const float4*)(aptr + k0);
        As[ak4+0][arow]=av.x; As[ak4+1][arow]=av.y;
        As[ak4+2][arow]=av.z; As[ak4+3][arow]=av.w;
        float4 bv = *(const float4*)(bptr + (size_t)k0*FDIM);
        *(float4*)(&Bs[bk][bc4]) = bv;
        __syncthreads();
        #pragma unroll
        for (int kk=0;kk<16;kk++){
            float a0=As[kk][ty*4+0], a1=As[kk][ty*4+1];
            float a2=As[kk][ty*4+2], a3=As[kk][ty*4+3];
            float4 b = *(const float4*)(&Bs[kk][tx*4]);
            acc[0][0]+=a0*b.x; acc[0][1]+=a0*b.y; acc[0][2]+=a0*b.z; acc[0][3]+=a0*b.w;
            acc[1][0]+=a1*b.x; acc[1][1]+=a1*b.y; acc[1][2]+=a1*b.z; acc[1][3]+=a1*b.w;
            acc[2][0]+=a2*b.x; acc[2][1]+=a2*b.y; acc[2][2]+=a2*b.z; acc[2][3]+=a2*b.w;
            acc[3][0]+=a3*b.x; acc[3][1]+=a3*b.y; acc[3][2]+=a3*b.z; acc[3][3]+=a3*b.w;
        }
        __syncthreads();
    }
    float4 bb = *(const float4*)(b1l + (size_t)e*FDIM + n0 + tx*4);
    #pragma unroll
    for (int ii=0;ii<4;ii++){
        int i = m0 + ty*4 + ii;
        if (i < cnt){
            size_t r = (size_t)(off + i);
            float4 hv;
            hv.x = gelu_tanh(acc[ii][0]+bb.x);
            hv.y = gelu_tanh(acc[ii][1]+bb.y);
            hv.z = gelu_tanh(acc[ii][2]+bb.z);
            hv.w = gelu_tanh(acc[ii][3]+bb.w);
            *(float4*)(&g_H[r*FDIM + n0 + tx*4]) = hv;
        }
    }
}

// ---------------- GEMM2: Y = H @ w2[e] + b2[e] ----------------
__global__ void __launch_bounds__(256) gemm2_kernel(const float* __restrict__ w2l,
                                                    const float* __restrict__ b2l){
    int e   = blockIdx.z;
    int cnt = g_cnt[e];
    int m0  = blockIdx.y*64;
    if (m0 >= cnt) return;
    int off = g_off[e];
    int n0  = blockIdx.x*64;

    __shared__ float As[16][65];
    __shared__ __align__(16) float Bs[16][64];
    int tid = threadIdx.x;
    int tx = tid & 15, ty = tid >> 4;
    int arow = tid >> 2, ak4 = (tid & 3)*4;
    int bk = tid >> 4, bc4 = (tid & 15)*4;

    int ai = m0 + arow; if (ai >= cnt) ai = cnt-1;
    const float* aptr = g_H + (size_t)(off+ai)*FDIM + ak4;
    const float* bptr = w2l + (size_t)e*FDIM*DDIM + (size_t)bk*DDIM + n0 + bc4;

    float acc[4][4] = {};
    for (int k0=0;k0<FDIM;k0+=16){
        float4 av = *(const float4*)(aptr + k0);
        As[ak4+0][arow]=av.x; As[ak4+1][arow]=av.y;
        As[ak4+2][arow]=av.z; As[ak4+3][arow]=av.w;
        float4 bv = *(const float4*)(bptr + (size_t)k0*DDIM);
        *(float4*)(&Bs[bk][bc4]) = bv;
        __syncthreads();
        #pragma unroll
        for (int kk=0;kk<16;kk++){
            float a0=As[kk][ty*4+0], a1=As[kk][ty*4+1];
            float a2=As[kk][ty*4+2], a3=As[kk][ty*4+3];
            float4 b = *(const float4*)(&Bs[kk][tx*4]);
            acc[0][0]+=a0*b.x; acc[0][1]+=a0*b.y; acc[0][2]+=a0*b.z; acc[0][3]+=a0*b.w;
            acc[1][0]+=a1*b.x; acc[1][1]+=a1*b.y; acc[1][2]+=a1*b.z; acc[1][3]+=a1*b.w;
            acc[2][0]+=a2*b.x; acc[2][1]+=a2*b.y; acc[2][2]+=a2*b.z; acc[2][3]+=a2*b.w;
            acc[3][0]+=a3*b.x; acc[3][1]+=a3*b.y; acc[3][2]+=a3*b.z; acc[3][3]+=a3*b.w;
        }
        __syncthreads();
    }
    float4 bb = *(const float4*)(b2l + (size_t)e*DDIM + n0 + tx*4);
    #pragma unroll
    for (int ii=0;ii<4;ii++){
        int i = m0 + ty*4 + ii;
        if (i < cnt){
            size_t r = (size_t)(off + i);
            float4 yv;
            yv.x = acc[ii][0]+bb.x; yv.y = acc[ii][1]+bb.y;
            yv.z = acc[ii][2]+bb.z; yv.w = acc[ii][3]+bb.w;
            *(float4*)(&g_Y[r*DDIM + n0 + tx*4]) = yv;
        }
    }
}

// ---------------- combine: x += g1*Y1 + g2*Y2 (deterministic) ----------------
__global__ void combine_kernel(float* __restrict__ out){
    int t = blockIdx.x, tid = threadIdx.x;
    int r1 = g_tok_row[t*2+0], r2 = g_tok_row[t*2+1];
    float g1 = g_topv[t*2+0],  g2 = g_topv[t*2+1];
    const float* y1 = g_Y + (size_t)r1*DDIM;
    const float* y2 = g_Y + (size_t)r2*DDIM;
    #pragma unroll
    for (int q=0;q<4;q++){
        int d = q*256 + tid;
        out[(size_t)t*DDIM + d] += g1*y1[d] + g2*y2[d];
    }
}

__global__ void finish_kernel(float* __restrict__ out){
    out[(size_t)NTOK*DDIM] = g_loss;
}

// ---------------- launch ----------------
extern "C" void kernel_launch(void* const* d_in, const int* in_sizes, int n_in,
                              void* d_out, int out_size){
    const float* x  = (const float*)d_in[0];
    const float* wr = (const float*)d_in[1];
    const float* w1 = (const float*)d_in[2];
    const float* b1 = (const float*)d_in[3];
    const float* w2 = (const float*)d_in[4];
    const float* b2 = (const float*)d_in[5];
    float* out = (float*)d_out;

    init_kernel<<<NTOK, 1024>>>(x, out);   // NTOK*1024 == NTOK*DDIM elements

    for (int l=0;l<NLAY;l++){
        const float* wr_l = wr + (size_t)l*DDIM*NEXP;
        const float* w1_l = w1 + (size_t)l*NEXP*DDIM*FDIM;
        const float* b1_l = b1 + (size_t)l*NEXP*FDIM;
        const float* w2_l = w2 + (size_t)l*NEXP*FDIM*DDIM;
        const float* b2_l = b2 + (size_t)l*NEXP*DDIM;

        ln_kernel    <<<NTOK, 256>>>(out);
        router_kernel<<<NTOK, 256>>>(wr_l);
        stats_kernel <<<1, 256>>>();
        place_kernel <<<RTOT/256, 256>>>();
        gemm1_kernel <<<dim3(FDIM/64, NTOK/64, NEXP), 256>>>(w1_l, b1_l);
        gemm2_kernel <<<dim3(DDIM/64, NTOK/64, NEXP), 256>>>(w2_l, b2_l);
        combine_kernel<<<NTOK, 256>>>(out);
    }
    if (out_size > NTOK*DDIM) finish_kernel<<<1,1>>>(out);
}